// round 1
// baseline (speedup 1.0000x reference)
#include <cuda_runtime.h>

#define NMAX 100000
#define EMAX 1600000
#define GMAX 128

// ---------------- device scratch (no allocations allowed) ----------------
__device__ float    g_h[NMAX * 32];          // per-layer node features h = x@W
__device__ float    g_xl[3][NMAX * 32];      // GAT layer outputs (without bias)
__device__ float    g_asrc[NMAX];
__device__ float    g_adst[NMAX];
__device__ unsigned g_maxb[NMAX];            // ordered-uint segment max
__device__ float    g_sumb[NMAX];            // segment exp-sum (edges only)
__device__ float    g_invb[NMAX];            // 1/denominator
__device__ float    g_edge[EMAX];            // logit, then exp
__device__ float    g_easum[3];              // edge_attr column sums
// g_prm layout: [0..288) Weff(9x32), [288..320) beff(32), [320+5l..): u0,u1,u2,c,aloop
__device__ float    g_prm[352];
__device__ float    g_gsum[GMAX];
__device__ float    g_gcnt[GMAX];

// ---------------- helpers ----------------
__device__ __forceinline__ unsigned ford(float f) {
    unsigned u = __float_as_uint(f);
    return (u & 0x80000000u) ? ~u : (u | 0x80000000u);
}
__device__ __forceinline__ float funord(unsigned u) {
    return (u & 0x80000000u) ? __uint_as_float(u & 0x7FFFFFFFu) : __uint_as_float(~u);
}
__device__ __forceinline__ float lrelu(float x) { return x > 0.f ? x : 0.2f * x; }
__device__ __forceinline__ float wreduce(float v) {
#pragma unroll
    for (int o = 16; o; o >>= 1) v += __shfl_down_sync(0xffffffffu, v, o);
    return v;
}

// ---------------- init: zero small accumulators ----------------
__global__ void k_init() {
    int t = threadIdx.x;
    if (t < 3) g_easum[t] = 0.f;
    if (t < GMAX) { g_gsum[t] = 0.f; g_gcnt[t] = 0.f; }
}

// ---------------- edge_attr column sums ----------------
__global__ void k_easum(const float* __restrict__ ea, int E) {
    float s0 = 0.f, s1 = 0.f, s2 = 0.f;
    for (int e = blockIdx.x * blockDim.x + threadIdx.x; e < E; e += gridDim.x * blockDim.x) {
        s0 += ea[3 * e];
        s1 += ea[3 * e + 1];
        s2 += ea[3 * e + 2];
    }
    s0 = wreduce(s0); s1 = wreduce(s1); s2 = wreduce(s2);
    if ((threadIdx.x & 31) == 0) {
        atomicAdd(&g_easum[0], s0);
        atomicAdd(&g_easum[1], s1);
        atomicAdd(&g_easum[2], s2);
    }
}

// ---------------- precompute folded parameters ----------------
__global__ void k_prep(const float* __restrict__ W_ne, const float* __restrict__ b_ne,
                       const float* __restrict__ W_ee, const float* __restrict__ b_ee,
                       const float* __restrict__ W0,
                       const float* __restrict__ We0, const float* __restrict__ ae0,
                       const float* __restrict__ We1, const float* __restrict__ ae1,
                       const float* __restrict__ We2, const float* __restrict__ ae2,
                       int E) {
    int t = threadIdx.x;
    if (t < 288) {               // Weff[r*32+j] = sum_d W_ne[r,d]*W0[d,j]
        int r = t / 32, j = t % 32;
        float s = 0.f;
        for (int d = 0; d < 16; d++) s += W_ne[r * 16 + d] * W0[d * 32 + j];
        g_prm[t] = s;
    } else if (t < 320) {        // beff[j] = sum_d b_ne[d]*W0[d,j]
        int j = t - 288;
        float s = 0.f;
        for (int d = 0; d < 16; d++) s += b_ne[d] * W0[d * 32 + j];
        g_prm[288 + j] = s;
    }
    if (t == 0) {
        const float* Wes[3] = {We0, We1, We2};
        const float* aes[3] = {ae0, ae1, ae2};
        float inv = 1.f / (float)E;
        float m0 = g_easum[0] * inv, m1 = g_easum[1] * inv, m2 = g_easum[2] * inv;
        for (int l = 0; l < 3; l++) {
            float v0 = 0.f, v1 = 0.f;
            for (int j = 0; j < 32; j++) {
                v0 += Wes[l][j] * aes[l][j];
                v1 += Wes[l][32 + j] * aes[l][j];
            }
            float u0 = W_ee[0] * v0 + W_ee[1] * v1;
            float u1 = W_ee[2] * v0 + W_ee[3] * v1;
            float u2 = W_ee[4] * v0 + W_ee[5] * v1;
            float c  = b_ee[0] * v0 + b_ee[1] * v1;
            float aloop = m0 * u0 + m1 * u1 + m2 * u2 + c;
            g_prm[320 + 5 * l + 0] = u0;
            g_prm[320 + 5 * l + 1] = u1;
            g_prm[320 + 5 * l + 2] = u2;
            g_prm[320 + 5 * l + 3] = c;
            g_prm[320 + 5 * l + 4] = aloop;
        }
    }
}

// ---------------- layer-0 node kernel: h = nf@Weff + beff, attn scalars, init ----------------
__global__ void k_node0(const float* __restrict__ nf,
                        const float* __restrict__ as_, const float* __restrict__ ad_,
                        int n) {
    __shared__ float Ws[288], bs[32], ass[32], ads[32];
    int t = threadIdx.x;
    for (int k = t; k < 288; k += blockDim.x) Ws[k] = g_prm[k];
    if (t < 32) { bs[t] = g_prm[288 + t]; ass[t] = as_[t]; ads[t] = ad_[t]; }
    __syncthreads();
    int i = blockIdx.x * (blockDim.x >> 5) + (t >> 5);
    if (i >= n) return;
    int j = t & 31;
    float xv = (j < 9) ? nf[i * 9 + j] : 0.f;
    float h = bs[j];
#pragma unroll
    for (int d = 0; d < 9; d++) {
        float xd = __shfl_sync(0xffffffffu, xv, d);
        h += xd * Ws[d * 32 + j];
    }
    g_h[i * 32 + j] = h;
    float sa = wreduce(h * ass[j]);
    float sd = wreduce(h * ads[j]);
    if (j == 0) {
        g_asrc[i] = sa;
        g_adst[i] = sd;
        float lg = lrelu(sa + sd + g_prm[320 + 4]);   // self-loop logit, layer 0
        g_maxb[i] = ford(lg);
        g_sumb[i] = 0.f;
    }
}

// ---------------- layer-1/2 node kernel ----------------
__global__ void k_node(int lprev, const float* __restrict__ W, const float* __restrict__ bbprev,
                       const float* __restrict__ as_, const float* __restrict__ ad_,
                       int lofs, int n) {
    __shared__ float Ws[1024], ass[32], ads[32], bbs[32];
    int t = threadIdx.x;
    for (int k = t; k < 1024; k += blockDim.x) Ws[k] = W[k];
    if (t < 32) { ass[t] = as_[t]; ads[t] = ad_[t]; bbs[t] = bbprev[t]; }
    __syncthreads();
    int i = blockIdx.x * (blockDim.x >> 5) + (t >> 5);
    if (i >= n) return;
    int j = t & 31;
    float xv = g_xl[lprev][i * 32 + j] + bbs[j];
    float h = 0.f;
#pragma unroll
    for (int d = 0; d < 32; d++) {
        float xd = __shfl_sync(0xffffffffu, xv, d);
        h += xd * Ws[d * 32 + j];
    }
    g_h[i * 32 + j] = h;
    float sa = wreduce(h * ass[j]);
    float sd = wreduce(h * ads[j]);
    if (j == 0) {
        g_asrc[i] = sa;
        g_adst[i] = sd;
        float lg = lrelu(sa + sd + g_prm[lofs + 4]);
        g_maxb[i] = ford(lg);
        g_sumb[i] = 0.f;
    }
}

// ---------------- edge pass A: logit + segment max ----------------
__global__ void k_edgeA(const int* __restrict__ src, const int* __restrict__ dst,
                        const float* __restrict__ ea, int E, int lofs) {
    int e = blockIdx.x * blockDim.x + threadIdx.x;
    if (e >= E) return;
    float u0 = g_prm[lofs], u1 = g_prm[lofs + 1], u2 = g_prm[lofs + 2], c = g_prm[lofs + 3];
    int s = src[e], d = dst[e];
    float aed = ea[3 * e] * u0 + ea[3 * e + 1] * u1 + ea[3 * e + 2] * u2 + c;
    float lg = lrelu(g_asrc[s] + g_adst[d] + aed);
    g_edge[e] = lg;
    atomicMax(&g_maxb[d], ford(lg));
}

// ---------------- edge pass B: exp + segment sum ----------------
__global__ void k_edgeB(const int* __restrict__ dst, int E) {
    int e = blockIdx.x * blockDim.x + threadIdx.x;
    if (e >= E) return;
    int d = dst[e];
    float mx = funord(g_maxb[d]);
    float ex = expf(g_edge[e] - mx);
    g_edge[e] = ex;
    atomicAdd(&g_sumb[d], ex);
}

// ---------------- node mid: self-loop contribution + inverse denominator ----------------
__global__ void k_mid(int lsel, int lofs, int n) {
    int t = threadIdx.x;
    int i = blockIdx.x * (blockDim.x >> 5) + (t >> 5);
    if (i >= n) return;
    int j = t & 31;
    float mx = funord(g_maxb[i]);
    float lg = lrelu(g_asrc[i] + g_adst[i] + g_prm[lofs + 4]);
    float le = expf(lg - mx);
    float inv = 1.f / (g_sumb[i] + le + 1e-16f);
    if (j == 0) g_invb[i] = inv;
    g_xl[lsel][i * 32 + j] = g_h[i * 32 + j] * (le * inv);
}

// ---------------- edge pass C: weighted aggregation (8 lanes / edge, float4) ----------------
__global__ void k_edgeC(const int* __restrict__ src, const int* __restrict__ dst,
                        int lsel, int E) {
    int idx = blockIdx.x * blockDim.x + threadIdx.x;
    int e = idx >> 3;
    if (e >= E) return;
    int r = idx & 7;
    int s = src[e], d = dst[e];
    float att = g_edge[e] * g_invb[d];
    float4 hv = reinterpret_cast<const float4*>(g_h)[s * 8 + r];
    float* o = &g_xl[lsel][d * 32 + r * 4];
    atomicAdd(o + 0, hv.x * att);
    atomicAdd(o + 1, hv.y * att);
    atomicAdd(o + 2, hv.z * att);
    atomicAdd(o + 3, hv.w * att);
}

// ---------------- readout: per-node scalar + per-graph sums ----------------
__global__ void k_readout(const int* __restrict__ batch, const float* __restrict__ Wl3,
                          const float* __restrict__ bb0, const float* __restrict__ bb1,
                          const float* __restrict__ bb2, int n) {
    __shared__ float w[96], b[96];
    int t = threadIdx.x;
    if (t < 96) w[t] = Wl3[t];
    if (t < 32) { b[t] = bb0[t]; b[32 + t] = bb1[t]; b[64 + t] = bb2[t]; }
    __syncthreads();
    int i = blockIdx.x * (blockDim.x >> 5) + (t >> 5);
    if (i >= n) return;
    int j = t & 31;
    float v = (g_xl[0][i * 32 + j] + b[j])      * w[j]
            + (g_xl[1][i * 32 + j] + b[32 + j]) * w[32 + j]
            + (g_xl[2][i * 32 + j] + b[64 + j]) * w[64 + j];
    v = wreduce(v);
    if (j == 0) {
        int g = batch[i];
        atomicAdd(&g_gsum[g], v);
        atomicAdd(&g_gcnt[g], 1.f);
    }
}

// ---------------- final: mean + linear bias ----------------
__global__ void k_final(float* __restrict__ out, const float* __restrict__ b_l3, int G) {
    int g = blockIdx.x * blockDim.x + threadIdx.x;
    if (g < G) out[g] = g_gsum[g] / fmaxf(g_gcnt[g], 1.f) + b_l3[0];
}

// ---------------- launch ----------------
extern "C" void kernel_launch(void* const* d_in, const int* in_sizes, int n_in,
                              void* d_out, int out_size) {
    const float* nf    = (const float*)d_in[0];
    const int*   ei    = (const int*)d_in[1];
    const float* ea    = (const float*)d_in[2];
    const int*   batch = (const int*)d_in[3];
    const float* W_ne  = (const float*)d_in[4];
    const float* b_ne  = (const float*)d_in[5];
    const float* W_ee  = (const float*)d_in[6];
    const float* b_ee  = (const float*)d_in[7];
    const float* W_l3  = (const float*)d_in[8];
    const float* b_l3  = (const float*)d_in[9];
    const float* W[3]  = {(const float*)d_in[10], (const float*)d_in[16], (const float*)d_in[22]};
    const float* as_[3] = {(const float*)d_in[11], (const float*)d_in[17], (const float*)d_in[23]};
    const float* ad_[3] = {(const float*)d_in[12], (const float*)d_in[18], (const float*)d_in[24]};
    const float* We_[3] = {(const float*)d_in[13], (const float*)d_in[19], (const float*)d_in[25]};
    const float* ae_[3] = {(const float*)d_in[14], (const float*)d_in[20], (const float*)d_in[26]};
    const float* bb_[3] = {(const float*)d_in[15], (const float*)d_in[21], (const float*)d_in[27]};

    int n = in_sizes[3];          // batch has N entries
    int E = in_sizes[1] / 2;      // edge_index is [2,E]
    int G = out_size;
    const int* src = ei;
    const int* dst = ei + E;

    k_init<<<1, 128>>>();
    k_easum<<<256, 256>>>(ea, E);
    k_prep<<<1, 320>>>(W_ne, b_ne, W_ee, b_ee, W[0],
                       We_[0], ae_[0], We_[1], ae_[1], We_[2], ae_[2], E);

    int nb  = (n + 7) / 8;            // warp per node, 256 threads/block
    int eb  = (E + 255) / 256;
    int ecb = (E * 8 + 255) / 256;

    for (int l = 0; l < 3; l++) {
        int lofs = 320 + 5 * l;
        if (l == 0)
            k_node0<<<nb, 256>>>(nf, as_[0], ad_[0], n);
        else
            k_node<<<nb, 256>>>(l - 1, W[l], bb_[l - 1], as_[l], ad_[l], lofs, n);
        k_edgeA<<<eb, 256>>>(src, dst, ea, E, lofs);
        k_edgeB<<<eb, 256>>>(dst, E);
        k_mid<<<nb, 256>>>(l, lofs, n);
        k_edgeC<<<ecb, 256>>>(src, dst, l, E);
    }

    k_readout<<<nb, 256>>>(batch, W_l3, bb_[0], bb_[1], bb_[2], n);
    k_final<<<1, 128>>>((float*)d_out, b_l3, G);
}

// round 2
// speedup vs baseline: 1.2372x; 1.2372x over previous
#include <cuda_runtime.h>

#define NMAX 100000
#define EMAX 1600000
#define GMAX 128

// ---------------- device scratch ----------------
__device__ float    g_h[NMAX * 32];           // node features h = x@W (current layer)
__device__ float    g_xl[3][NMAX * 32];       // GAT layer outputs (without bias)
__device__ float    g_asrc[NMAX];
__device__ float    g_adst[NMAX];
__device__ int      g_deg[NMAX];
__device__ int      g_rp[NMAX + 1];           // CSR row pointers (by dst)
__device__ int      g_cur[NMAX];              // scatter cursors
__device__ int      g_csrc[EMAX];             // CSR: src node per slot
__device__ float    g_cae[3 * EMAX];          // CSR: per-layer edge logit term
__device__ float    g_easum[3];
// g_prm: [0..288) Weff(9x32), [288..320) beff, [320+5l..): u0,u1,u2,c,aloop
__device__ float    g_prm[352];
__device__ float    g_gsum[GMAX];
__device__ float    g_gcnt[GMAX];

__device__ __forceinline__ float lrelu(float x) { return x > 0.f ? x : 0.2f * x; }
__device__ __forceinline__ float wreduce(float v) {
#pragma unroll
    for (int o = 16; o; o >>= 1) v += __shfl_xor_sync(0xffffffffu, v, o);
    return v;
}

// ---------------- init ----------------
__global__ void k_init() {
    int t = threadIdx.x;
    if (t < 3) g_easum[t] = 0.f;
    if (t < GMAX) { g_gsum[t] = 0.f; g_gcnt[t] = 0.f; }
}
__global__ void k_zero_deg(int n) {
    int i = blockIdx.x * blockDim.x + threadIdx.x;
    if (i < n) g_deg[i] = 0;
}

// ---------------- edge_attr column sums ----------------
__global__ void k_easum(const float* __restrict__ ea, int E) {
    float s0 = 0.f, s1 = 0.f, s2 = 0.f;
    for (int e = blockIdx.x * blockDim.x + threadIdx.x; e < E; e += gridDim.x * blockDim.x) {
        s0 += ea[3 * e]; s1 += ea[3 * e + 1]; s2 += ea[3 * e + 2];
    }
    s0 = wreduce(s0); s1 = wreduce(s1); s2 = wreduce(s2);
    if ((threadIdx.x & 31) == 0) {
        atomicAdd(&g_easum[0], s0); atomicAdd(&g_easum[1], s1); atomicAdd(&g_easum[2], s2);
    }
}

// ---------------- folded parameters ----------------
__global__ void k_prep(const float* __restrict__ W_ne, const float* __restrict__ b_ne,
                       const float* __restrict__ W_ee, const float* __restrict__ b_ee,
                       const float* __restrict__ W0,
                       const float* __restrict__ We0, const float* __restrict__ ae0,
                       const float* __restrict__ We1, const float* __restrict__ ae1,
                       const float* __restrict__ We2, const float* __restrict__ ae2,
                       int E) {
    int t = threadIdx.x;
    if (t < 288) {
        int r = t / 32, j = t % 32;
        float s = 0.f;
        for (int d = 0; d < 16; d++) s += W_ne[r * 16 + d] * W0[d * 32 + j];
        g_prm[t] = s;
    } else if (t < 320) {
        int j = t - 288;
        float s = 0.f;
        for (int d = 0; d < 16; d++) s += b_ne[d] * W0[d * 32 + j];
        g_prm[288 + j] = s;
    }
    if (t == 0) {
        const float* Wes[3] = {We0, We1, We2};
        const float* aes[3] = {ae0, ae1, ae2};
        float inv = 1.f / (float)E;
        float m0 = g_easum[0] * inv, m1 = g_easum[1] * inv, m2 = g_easum[2] * inv;
        for (int l = 0; l < 3; l++) {
            float v0 = 0.f, v1 = 0.f;
            for (int j = 0; j < 32; j++) {
                v0 += Wes[l][j] * aes[l][j];
                v1 += Wes[l][32 + j] * aes[l][j];
            }
            float u0 = W_ee[0] * v0 + W_ee[1] * v1;
            float u1 = W_ee[2] * v0 + W_ee[3] * v1;
            float u2 = W_ee[4] * v0 + W_ee[5] * v1;
            float c  = b_ee[0] * v0 + b_ee[1] * v1;
            g_prm[320 + 5 * l + 0] = u0;
            g_prm[320 + 5 * l + 1] = u1;
            g_prm[320 + 5 * l + 2] = u2;
            g_prm[320 + 5 * l + 3] = c;
            g_prm[320 + 5 * l + 4] = m0 * u0 + m1 * u1 + m2 * u2 + c;
        }
    }
}

// ---------------- CSR build ----------------
__global__ void k_count(const int* __restrict__ dst, int E) {
    int e = blockIdx.x * blockDim.x + threadIdx.x;
    if (e < E) atomicAdd(&g_deg[dst[e]], 1);
}

__global__ void k_scan(int n) {
    __shared__ int ssum[1024];
    int t = threadIdx.x;
    int per = (n + 1023) / 1024;
    int b0 = t * per, b1 = min(n, b0 + per);
    int s = 0;
    for (int i = b0; i < b1; i++) s += g_deg[i];
    ssum[t] = s;
    __syncthreads();
    for (int o = 1; o < 1024; o <<= 1) {
        int v = (t >= o) ? ssum[t - o] : 0;
        __syncthreads();
        ssum[t] += v;
        __syncthreads();
    }
    int run = t ? ssum[t - 1] : 0;
    for (int i = b0; i < b1; i++) {
        g_rp[i] = run; g_cur[i] = run;
        run += g_deg[i];
    }
    if (t == 1023) g_rp[n] = run;
}

__global__ void k_scatter(const int* __restrict__ src, const int* __restrict__ dst,
                          const float* __restrict__ ea, int E) {
    int e = blockIdx.x * blockDim.x + threadIdx.x;
    if (e >= E) return;
    int d = dst[e];
    int pos = atomicAdd(&g_cur[d], 1);
    g_csrc[pos] = src[e];
    float e0 = ea[3 * e], e1 = ea[3 * e + 1], e2 = ea[3 * e + 2];
#pragma unroll
    for (int l = 0; l < 3; l++) {
        const float* p = &g_prm[320 + 5 * l];
        g_cae[l * EMAX + pos] = e0 * p[0] + e1 * p[1] + e2 * p[2] + p[3];
    }
}

// ---------------- layer-0 node kernel (thread per node, smem tiled) ----------------
__global__ void __launch_bounds__(128) k_node0(const float* __restrict__ nf,
                                               const float* __restrict__ as_,
                                               const float* __restrict__ ad_, int n) {
    __shared__ float Ws[288], bs[32], av[64];
    __shared__ float xs[128 * 9];
    __shared__ float hs[128 * 33];
    int t = threadIdx.x;
    for (int k = t; k < 288; k += 128) Ws[k] = g_prm[k];
    if (t < 32) { bs[t] = g_prm[288 + t]; av[t] = as_[t]; av[32 + t] = ad_[t]; }
    int base = blockIdx.x * 128;
    int nblk = min(128, n - base);
    for (int k = t; k < nblk * 9; k += 128) xs[k] = nf[base * 9 + k];
    __syncthreads();
    if (t < nblk) {
        float acc[32];
#pragma unroll
        for (int j = 0; j < 32; j++) acc[j] = bs[j];
#pragma unroll
        for (int d = 0; d < 9; d++) {
            float xd = xs[t * 9 + d];
#pragma unroll
            for (int j = 0; j < 32; j++) acc[j] += xd * Ws[d * 32 + j];
        }
        float sa = 0.f, sd = 0.f;
#pragma unroll
        for (int j = 0; j < 32; j++) {
            sa += acc[j] * av[j]; sd += acc[j] * av[32 + j];
            hs[t * 33 + j] = acc[j];
        }
        g_asrc[base + t] = sa;
        g_adst[base + t] = sd;
    }
    __syncthreads();
    for (int k = t; k < nblk * 32; k += 128)
        g_h[base * 32 + k] = hs[(k >> 5) * 33 + (k & 31)];
}

// ---------------- layer-1/2 node kernel ----------------
__global__ void __launch_bounds__(128) k_node(int lprev, const float* __restrict__ W,
                                              const float* __restrict__ bbprev,
                                              const float* __restrict__ as_,
                                              const float* __restrict__ ad_, int n) {
    __shared__ float Ws[1024], av[64], bbs[32];
    __shared__ float xs[128 * 33];
    int t = threadIdx.x;
    for (int k = t; k < 1024; k += 128) Ws[k] = W[k];
    if (t < 32) { av[t] = as_[t]; av[32 + t] = ad_[t]; bbs[t] = bbprev[t]; }
    __syncthreads();
    int base = blockIdx.x * 128;
    int nblk = min(128, n - base);
    const float* xin = g_xl[lprev] + base * 32;
    for (int k = t; k < nblk * 32; k += 128)
        xs[(k >> 5) * 33 + (k & 31)] = xin[k] + bbs[k & 31];
    __syncthreads();
    float acc[32];
    if (t < nblk) {
#pragma unroll
        for (int j = 0; j < 32; j++) acc[j] = 0.f;
#pragma unroll
        for (int d = 0; d < 32; d++) {
            float xd = xs[t * 33 + d];
#pragma unroll
            for (int j = 0; j < 32; j++) acc[j] += xd * Ws[d * 32 + j];
        }
    }
    __syncthreads();
    if (t < nblk) {
        float sa = 0.f, sd = 0.f;
#pragma unroll
        for (int j = 0; j < 32; j++) {
            sa += acc[j] * av[j]; sd += acc[j] * av[32 + j];
            xs[t * 33 + j] = acc[j];
        }
        g_asrc[base + t] = sa;
        g_adst[base + t] = sd;
    }
    __syncthreads();
    for (int k = t; k < nblk * 32; k += 128)
        g_h[base * 32 + k] = xs[(k >> 5) * 33 + (k & 31)];
}

// ---------------- fused softmax + aggregation (warp per dst node) ----------------
__global__ void __launch_bounds__(256) k_agg(int l, int lofs, int n) {
    int t = threadIdx.x, j = t & 31;
    int d = blockIdx.x * (blockDim.x >> 5) + (t >> 5);
    if (d >= n) return;
    int beg = g_rp[d], end = g_rp[d + 1];
    float adst_d = g_adst[d];
    const float* cae = g_cae + (size_t)l * EMAX;
    float acc0 = 0.f, acc1 = 0.f, denom = 0.f;
    for (int base = beg; base < end; base += 32) {
        int idx = base + j;
        bool v = idx < end;
        int s = 0; float ex = 0.f;
        if (v) {
            s = g_csrc[idx];
            ex = expf(lrelu(g_asrc[s] + adst_d + cae[idx]));
        }
        denom += ex;
        int cnt = min(end - base, 32);
        for (int k = 0; k + 1 < cnt; k += 2) {
            float e0 = __shfl_sync(0xffffffffu, ex, k);
            int   s0 = __shfl_sync(0xffffffffu, s, k);
            float e1 = __shfl_sync(0xffffffffu, ex, k + 1);
            int   s1 = __shfl_sync(0xffffffffu, s, k + 1);
            acc0 += e0 * g_h[s0 * 32 + j];
            acc1 += e1 * g_h[s1 * 32 + j];
        }
        if (cnt & 1) {
            float e0 = __shfl_sync(0xffffffffu, ex, cnt - 1);
            int   s0 = __shfl_sync(0xffffffffu, s, cnt - 1);
            acc0 += e0 * g_h[s0 * 32 + j];
        }
    }
    denom = wreduce(denom);
    float le = expf(lrelu(g_asrc[d] + adst_d + g_prm[lofs + 4]));
    float inv = 1.f / (denom + le + 1e-16f);
    g_xl[l][d * 32 + j] = (acc0 + acc1 + le * g_h[d * 32 + j]) * inv;
}

// ---------------- readout ----------------
__global__ void k_readout(const int* __restrict__ batch, const float* __restrict__ Wl3,
                          const float* __restrict__ bb0, const float* __restrict__ bb1,
                          const float* __restrict__ bb2, int n) {
    __shared__ float w[96], b[96];
    int t = threadIdx.x;
    if (t < 96) w[t] = Wl3[t];
    if (t < 32) { b[t] = bb0[t]; b[32 + t] = bb1[t]; b[64 + t] = bb2[t]; }
    __syncthreads();
    int i = blockIdx.x * (blockDim.x >> 5) + (t >> 5);
    if (i >= n) return;
    int j = t & 31;
    float v = (g_xl[0][i * 32 + j] + b[j])      * w[j]
            + (g_xl[1][i * 32 + j] + b[32 + j]) * w[32 + j]
            + (g_xl[2][i * 32 + j] + b[64 + j]) * w[64 + j];
    v = wreduce(v);
    if (j == 0) {
        int g = batch[i];
        atomicAdd(&g_gsum[g], v);
        atomicAdd(&g_gcnt[g], 1.f);
    }
}

__global__ void k_final(float* __restrict__ out, const float* __restrict__ b_l3, int G) {
    int g = blockIdx.x * blockDim.x + threadIdx.x;
    if (g < G) out[g] = g_gsum[g] / fmaxf(g_gcnt[g], 1.f) + b_l3[0];
}

// ---------------- launch ----------------
extern "C" void kernel_launch(void* const* d_in, const int* in_sizes, int n_in,
                              void* d_out, int out_size) {
    const float* nf    = (const float*)d_in[0];
    const int*   ei    = (const int*)d_in[1];
    const float* ea    = (const float*)d_in[2];
    const int*   batch = (const int*)d_in[3];
    const float* W_ne  = (const float*)d_in[4];
    const float* b_ne  = (const float*)d_in[5];
    const float* W_ee  = (const float*)d_in[6];
    const float* b_ee  = (const float*)d_in[7];
    const float* W_l3  = (const float*)d_in[8];
    const float* b_l3  = (const float*)d_in[9];
    const float* W[3]   = {(const float*)d_in[10], (const float*)d_in[16], (const float*)d_in[22]};
    const float* as_[3] = {(const float*)d_in[11], (const float*)d_in[17], (const float*)d_in[23]};
    const float* ad_[3] = {(const float*)d_in[12], (const float*)d_in[18], (const float*)d_in[24]};
    const float* We_[3] = {(const float*)d_in[13], (const float*)d_in[19], (const float*)d_in[25]};
    const float* ae_[3] = {(const float*)d_in[14], (const float*)d_in[20], (const float*)d_in[26]};
    const float* bb_[3] = {(const float*)d_in[15], (const float*)d_in[21], (const float*)d_in[27]};

    int n = in_sizes[3];
    int E = in_sizes[1] / 2;
    int G = out_size;
    const int* src = ei;
    const int* dst = ei + E;

    int eb = (E + 255) / 256;
    int nb128 = (n + 127) / 128;
    int nbw = (n + 7) / 8;

    k_init<<<1, 128>>>();
    k_zero_deg<<<(n + 255) / 256, 256>>>(n);
    k_easum<<<256, 256>>>(ea, E);
    k_prep<<<1, 320>>>(W_ne, b_ne, W_ee, b_ee, W[0],
                       We_[0], ae_[0], We_[1], ae_[1], We_[2], ae_[2], E);
    k_count<<<eb, 256>>>(dst, E);
    k_scan<<<1, 1024>>>(n);
    k_scatter<<<eb, 256>>>(src, dst, ea, E);

    for (int l = 0; l < 3; l++) {
        int lofs = 320 + 5 * l;
        if (l == 0)
            k_node0<<<nb128, 128>>>(nf, as_[0], ad_[0], n);
        else
            k_node<<<nb128, 128>>>(l - 1, W[l], bb_[l - 1], as_[l], ad_[l], n);
        k_agg<<<nbw, 256>>>(l, lofs, n);
    }

    k_readout<<<nbw, 256>>>(batch, W_l3, bb_[0], bb_[1], bb_[2], n);
    k_final<<<1, 128>>>((float*)d_out, b_l3, G);
}

// round 3
// speedup vs baseline: 1.2692x; 1.0259x over previous
#include <cuda_runtime.h>

#define NMAX 100000
#define EMAX 1600000
#define GMAX 128

// ---------------- device scratch ----------------
__device__ float  g_ha[NMAX * 32];       // h double buffer A
__device__ float  g_hb[NMAX * 32];       // h double buffer B
__device__ float  g_x1[NMAX * 32];       // layer-1 output (for readout)
__device__ float  g_x2[NMAX * 32];       // layer-2 output (for readout)
__device__ float  g_as[2][NMAX];         // asrc double buffer
__device__ float  g_ad[2][NMAX];         // adst double buffer
__device__ int    g_deg[NMAX];
__device__ int    g_rp[NMAX + 1];
__device__ int    g_cur[NMAX];
__device__ float4 g_pack[EMAX];          // {src_bits, cae0, cae1, cae2} in CSR order
__device__ float  g_easum[3];
// g_prm: [0..288) Weff(9x32), [288..320) beff, [320+5l..): u0,u1,u2,c,aloop
__device__ float  g_prm[352];
__device__ float  g_gsum[GMAX];
__device__ float  g_gcnt[GMAX];

__device__ __forceinline__ float lrelu(float x) { return x > 0.f ? x : 0.2f * x; }
__device__ __forceinline__ float wreduce(float v) {
#pragma unroll
    for (int o = 16; o; o >>= 1) v += __shfl_xor_sync(0xffffffffu, v, o);
    return v;
}

// ---------------- A: init ----------------
__global__ void k_initA(int n) {
    int i = blockIdx.x * blockDim.x + threadIdx.x;
    if (i < n) g_deg[i] = 0;
    if (blockIdx.x == 0) {
        int t = threadIdx.x;
        if (t < 3) g_easum[t] = 0.f;
        if (t < GMAX) { g_gsum[t] = 0.f; g_gcnt[t] = 0.f; }
    }
}

// ---------------- B: degree count + edge_attr column sums ----------------
__global__ void k_countB(const int* __restrict__ dst, const float* __restrict__ ea, int E) {
    __shared__ float sh[3];
    if (threadIdx.x < 3) sh[threadIdx.x] = 0.f;
    __syncthreads();
    float s0 = 0.f, s1 = 0.f, s2 = 0.f;
    for (int e = blockIdx.x * blockDim.x + threadIdx.x; e < E; e += gridDim.x * blockDim.x) {
        atomicAdd(&g_deg[dst[e]], 1);
        s0 += ea[3 * e]; s1 += ea[3 * e + 1]; s2 += ea[3 * e + 2];
    }
    s0 = wreduce(s0); s1 = wreduce(s1); s2 = wreduce(s2);
    if ((threadIdx.x & 31) == 0) {
        atomicAdd(&sh[0], s0); atomicAdd(&sh[1], s1); atomicAdd(&sh[2], s2);
    }
    __syncthreads();
    if (threadIdx.x < 3) atomicAdd(&g_easum[threadIdx.x], sh[threadIdx.x]);
}

// ---------------- C: folded params + CSR scan (single block, 1024 threads) ----------------
__global__ void k_scanprep(const float* __restrict__ W_ne, const float* __restrict__ b_ne,
                           const float* __restrict__ W_ee, const float* __restrict__ b_ee,
                           const float* __restrict__ W0,
                           const float* __restrict__ We0, const float* __restrict__ ae0,
                           const float* __restrict__ We1, const float* __restrict__ ae1,
                           const float* __restrict__ We2, const float* __restrict__ ae2,
                           int n, int E) {
    int t = threadIdx.x;
    // --- prep part ---
    if (t < 288) {
        int r = t / 32, j = t % 32;
        float s = 0.f;
        for (int d = 0; d < 16; d++) s += W_ne[r * 16 + d] * W0[d * 32 + j];
        g_prm[t] = s;
    } else if (t < 320) {
        int j = t - 288;
        float s = 0.f;
        for (int d = 0; d < 16; d++) s += b_ne[d] * W0[d * 32 + j];
        g_prm[288 + j] = s;
    } else if (t < 416) {
        int l = (t - 320) >> 5, j = t & 31;
        const float* We = (l == 0) ? We0 : (l == 1) ? We1 : We2;
        const float* ae = (l == 0) ? ae0 : (l == 1) ? ae1 : ae2;
        float aej = ae[j];
        float v0 = wreduce(We[j] * aej);
        float v1 = wreduce(We[32 + j] * aej);
        if (j == 0) {
            float u0 = W_ee[0] * v0 + W_ee[1] * v1;
            float u1 = W_ee[2] * v0 + W_ee[3] * v1;
            float u2 = W_ee[4] * v0 + W_ee[5] * v1;
            float c  = b_ee[0] * v0 + b_ee[1] * v1;
            float inv = 1.f / (float)E;
            g_prm[320 + 5 * l + 0] = u0;
            g_prm[320 + 5 * l + 1] = u1;
            g_prm[320 + 5 * l + 2] = u2;
            g_prm[320 + 5 * l + 3] = c;
            g_prm[320 + 5 * l + 4] = g_easum[0] * inv * u0 + g_easum[1] * inv * u1
                                   + g_easum[2] * inv * u2 + c;
        }
    }
    // --- scan part ---
    __shared__ int ssum[1024];
    int per = (n + 1023) / 1024;
    int b0 = t * per, b1 = min(n, b0 + per);
    int s = 0;
    for (int i = b0; i < b1; i++) s += g_deg[i];
    ssum[t] = s;
    __syncthreads();
    for (int o = 1; o < 1024; o <<= 1) {
        int v = (t >= o) ? ssum[t - o] : 0;
        __syncthreads();
        ssum[t] += v;
        __syncthreads();
    }
    int run = t ? ssum[t - 1] : 0;
    for (int i = b0; i < b1; i++) {
        g_rp[i] = run; g_cur[i] = run;
        run += g_deg[i];
    }
    if (t == 1023) g_rp[n] = run;
}

// ---------------- D: CSR scatter (blocks < eb) + layer-0 node matmul (rest) ----------------
__global__ void __launch_bounds__(256) k_build(const int* __restrict__ src,
                                               const int* __restrict__ dst,
                                               const float* __restrict__ ea,
                                               const float* __restrict__ nf,
                                               const float* __restrict__ as0,
                                               const float* __restrict__ ad0,
                                               int E, int n, int eb) {
    if ((int)blockIdx.x < eb) {
        int e = blockIdx.x * 256 + threadIdx.x;
        if (e >= E) return;
        int d = dst[e];
        int pos = atomicAdd(&g_cur[d], 1);
        float e0 = ea[3 * e], e1 = ea[3 * e + 1], e2 = ea[3 * e + 2];
        const float* p = &g_prm[320];
        float4 r;
        r.x = __int_as_float(src[e]);
        r.y = e0 * p[0]  + e1 * p[1]  + e2 * p[2]  + p[3];
        r.z = e0 * p[5]  + e1 * p[6]  + e2 * p[7]  + p[8];
        r.w = e0 * p[10] + e1 * p[11] + e2 * p[12] + p[13];
        g_pack[pos] = r;
    } else {
        __shared__ float Ws[288], bs[32], av[64];
        int t = threadIdx.x;
        for (int k = t; k < 288; k += 256) Ws[k] = g_prm[k];
        if (t < 32) { bs[t] = g_prm[288 + t]; av[t] = as0[t]; av[32 + t] = ad0[t]; }
        __syncthreads();
        int i = ((int)blockIdx.x - eb) * 256 + t;
        if (i >= n) return;
        float x[9];
#pragma unroll
        for (int r = 0; r < 9; r++) x[r] = nf[i * 9 + r];
        float acc[32];
#pragma unroll
        for (int j = 0; j < 32; j++) acc[j] = bs[j];
#pragma unroll
        for (int r = 0; r < 9; r++)
#pragma unroll
            for (int j = 0; j < 32; j++) acc[j] += x[r] * Ws[r * 32 + j];
        float sa = 0.f, sd = 0.f;
#pragma unroll
        for (int j = 0; j < 32; j++) { sa += acc[j] * av[j]; sd += acc[j] * av[32 + j]; }
        g_as[0][i] = sa; g_ad[0][i] = sd;
        float4* o = (float4*)&g_ha[i * 32];
#pragma unroll
        for (int q = 0; q < 8; q++)
            o[q] = make_float4(acc[4 * q], acc[4 * q + 1], acc[4 * q + 2], acc[4 * q + 3]);
    }
}

// ---------------- core gather body ----------------
template <int L>
__device__ __forceinline__ float agg_node(int d, int j, const float* __restrict__ hc,
                                          const float* __restrict__ asc, float adst_d,
                                          float aloop, float asrc_d) {
    int beg = g_rp[d], end = g_rp[d + 1];
    float acc0 = 0.f, acc1 = 0.f, acc2 = 0.f, acc3 = 0.f, denom = 0.f;
    for (int base = beg; base < end; base += 32) {
        int idx = base + j;
        int s = 0; float ex = 0.f;
        if (idx < end) {
            float4 r = g_pack[idx];
            s = __float_as_int(r.x);
            float ae = (L == 0) ? r.y : (L == 1) ? r.z : r.w;
            ex = __expf(lrelu(asc[s] + adst_d + ae));
        }
        denom += ex;
        int cnt = min(end - base, 32);
        int k = 0;
        for (; k + 3 < cnt; k += 4) {
            float e0 = __shfl_sync(0xffffffffu, ex, k);     int s0 = __shfl_sync(0xffffffffu, s, k);
            float e1 = __shfl_sync(0xffffffffu, ex, k + 1); int s1 = __shfl_sync(0xffffffffu, s, k + 1);
            float e2 = __shfl_sync(0xffffffffu, ex, k + 2); int s2 = __shfl_sync(0xffffffffu, s, k + 2);
            float e3 = __shfl_sync(0xffffffffu, ex, k + 3); int s3 = __shfl_sync(0xffffffffu, s, k + 3);
            acc0 += e0 * hc[s0 * 32 + j];
            acc1 += e1 * hc[s1 * 32 + j];
            acc2 += e2 * hc[s2 * 32 + j];
            acc3 += e3 * hc[s3 * 32 + j];
        }
        for (; k < cnt; k++) {
            float e0 = __shfl_sync(0xffffffffu, ex, k);     int s0 = __shfl_sync(0xffffffffu, s, k);
            acc0 += e0 * hc[s0 * 32 + j];
        }
    }
    denom = wreduce(denom);
    float le = __expf(lrelu(asrc_d + adst_d + aloop));
    float inv = 1.f / (denom + le + 1e-16f);
    return (acc0 + acc1 + acc2 + acc3 + le * hc[d * 32 + j]) * inv;
}

// ---------------- layer 0/1 agg: softmax-aggregate + NEXT layer node matmul fused ----------------
template <int L>
__global__ void __launch_bounds__(256) k_aggF(const float* __restrict__ Wn,
                                              const float* __restrict__ bbc,
                                              const float* __restrict__ asn,
                                              const float* __restrict__ adn, int n) {
    const float* hc = (L == 0) ? g_ha : g_hb;
    float*       hn = (L == 0) ? g_hb : g_ha;
    float*     xout = (L == 0) ? g_x1 : g_x2;
    constexpr int P = L & 1;
    __shared__ float Wns[1024], avs[64], bbs[32];
    int t = threadIdx.x, j = t & 31;
    for (int k = t; k < 1024; k += 256) Wns[k] = Wn[k];
    if (t < 32) { bbs[t] = bbc[t]; avs[t] = asn[t]; avs[32 + t] = adn[t]; }
    __syncthreads();
    int d = blockIdx.x * 8 + (t >> 5);
    if (d >= n) return;
    float adst_d = g_ad[P][d];
    float asrc_d = g_as[P][d];
    float aloop = g_prm[320 + 5 * L + 4];
    float xl = agg_node<L>(d, j, hc, g_as[P], adst_d, aloop, asrc_d);
    xout[d * 32 + j] = xl;
    // next-layer node transform: h' = (x + bb) @ Wn
    float y = xl + bbs[j];
    float h = 0.f;
#pragma unroll
    for (int d2 = 0; d2 < 32; d2++)
        h += __shfl_sync(0xffffffffu, y, d2) * Wns[d2 * 32 + j];
    hn[d * 32 + j] = h;
    float sa = wreduce(h * avs[j]);
    float sd = wreduce(h * avs[32 + j]);
    if (j == 0) { g_as[P ^ 1][d] = sa; g_ad[P ^ 1][d] = sd; }
}

// ---------------- layer 2 agg + readout fused ----------------
__global__ void __launch_bounds__(256) k_aggL(const int* __restrict__ batch,
                                              const float* __restrict__ Wl3,
                                              const float* __restrict__ bb0,
                                              const float* __restrict__ bb1,
                                              const float* __restrict__ bb2, int n) {
    __shared__ float w[96], b[96];
    int t = threadIdx.x, j = t & 31;
    if (t < 96) w[t] = Wl3[t];
    if (t < 32) { b[t] = bb0[t]; b[32 + t] = bb1[t]; b[64 + t] = bb2[t]; }
    __syncthreads();
    int d = blockIdx.x * 8 + (t >> 5);
    if (d >= n) return;
    float adst_d = g_ad[0][d];
    float asrc_d = g_as[0][d];
    float aloop = g_prm[320 + 5 * 2 + 4];
    float x3 = agg_node<2>(d, j, g_ha, g_as[0], adst_d, aloop, asrc_d);
    float v = (g_x1[d * 32 + j] + b[j])      * w[j]
            + (g_x2[d * 32 + j] + b[32 + j]) * w[32 + j]
            + (x3              + b[64 + j]) * w[64 + j];
    v = wreduce(v);
    if (j == 0) {
        int g = batch[d];
        atomicAdd(&g_gsum[g], v);
        atomicAdd(&g_gcnt[g], 1.f);
    }
}

__global__ void k_final(float* __restrict__ out, const float* __restrict__ b_l3, int G) {
    int g = blockIdx.x * blockDim.x + threadIdx.x;
    if (g < G) out[g] = g_gsum[g] / fmaxf(g_gcnt[g], 1.f) + b_l3[0];
}

// ---------------- launch ----------------
extern "C" void kernel_launch(void* const* d_in, const int* in_sizes, int n_in,
                              void* d_out, int out_size) {
    const float* nf    = (const float*)d_in[0];
    const int*   ei    = (const int*)d_in[1];
    const float* ea    = (const float*)d_in[2];
    const int*   batch = (const int*)d_in[3];
    const float* W_ne  = (const float*)d_in[4];
    const float* b_ne  = (const float*)d_in[5];
    const float* W_ee  = (const float*)d_in[6];
    const float* b_ee  = (const float*)d_in[7];
    const float* W_l3  = (const float*)d_in[8];
    const float* b_l3  = (const float*)d_in[9];
    const float* W[3]   = {(const float*)d_in[10], (const float*)d_in[16], (const float*)d_in[22]};
    const float* as_[3] = {(const float*)d_in[11], (const float*)d_in[17], (const float*)d_in[23]};
    const float* ad_[3] = {(const float*)d_in[12], (const float*)d_in[18], (const float*)d_in[24]};
    const float* We_[3] = {(const float*)d_in[13], (const float*)d_in[19], (const float*)d_in[25]};
    const float* ae_[3] = {(const float*)d_in[14], (const float*)d_in[20], (const float*)d_in[26]};
    const float* bb_[3] = {(const float*)d_in[15], (const float*)d_in[21], (const float*)d_in[27]};

    int n = in_sizes[3];
    int E = in_sizes[1] / 2;
    int G = out_size;
    const int* src = ei;
    const int* dst = ei + E;

    int eb  = (E + 255) / 256;
    int nb  = (n + 255) / 256;
    int nbw = (n + 7) / 8;

    k_initA<<<nb, 256>>>(n);
    k_countB<<<1184, 256>>>(dst, ea, E);
    k_scanprep<<<1, 1024>>>(W_ne, b_ne, W_ee, b_ee, W[0],
                            We_[0], ae_[0], We_[1], ae_[1], We_[2], ae_[2], n, E);
    k_build<<<eb + nb, 256>>>(src, dst, ea, nf, as_[0], ad_[0], E, n, eb);
    k_aggF<0><<<nbw, 256>>>(W[1], bb_[0], as_[1], ad_[1], n);
    k_aggF<1><<<nbw, 256>>>(W[2], bb_[1], as_[2], ad_[2], n);
    k_aggL<<<nbw, 256>>>(batch, W_l3, bb_[0], bb_[1], bb_[2], n);
    k_final<<<1, 128>>>((float*)d_out, b_l3, G);
}